// round 3
// baseline (speedup 1.0000x reference)
#include <cuda_runtime.h>

// DCTExtractor: gray = 0.299R + 0.587G + 0.114B over (64,3,512,512);
// per 8x8 block: D @ G @ D^T, elementwise * mask; output (64,1,512,512).
//
// Four threads per 8x8 tile (2-column slices). Column DCT accumulated on the
// fly (U = D @ G restricted to 2 cols, 16 regs); row-DCT partials reduced
// across the 4-thread group with a 2-stage shfl butterfly (xor2 then xor1).
// Purely HBM-bound: 201MB read + 67MB write; target ~6.5+ TB/s.

#define H 512
#define W 512
#define CHAN (H * W)
#define N_TILES (64 * 64 * 64)        // 262144
#define N_UNITS (N_TILES * 4)         // 1048576 quarter-tiles
#define THREADS 256

__global__ __launch_bounds__(THREADS, 4)
void dct_extract_kernel(const float* __restrict__ x,
                        const float* __restrict__ dctm,
                        const float* __restrict__ mask,
                        float* __restrict__ out)
{
    __shared__ float sD[64];
    __shared__ float sM[64];
    const int tid = threadIdx.x;
    if (tid < 64) {
        sD[tid] = dctm[tid];
        sM[tid] = mask[tid];
    }
    __syncthreads();

    const int gid = blockIdx.x * THREADS + tid;   // 0 .. N_UNITS-1
    const int q   = gid & 3;                      // quarter: cols 2q, 2q+1
    const int id  = gid >> 2;                     // tile id
    const int tw  = id & 63;
    const int th  = (id >> 6) & 63;
    const int b   = id >> 12;
    const int k0  = q * 2;                        // my first column in tile
    const int k1  = k0 + 1;

    const float* base = x + (size_t)b * 3 * CHAN
                          + (size_t)(th * 8) * W + (size_t)(tw * 8 + k0);

    // U[i][c] = sum_r D[i][r] * gray[r][c] for my 2 columns.
    float U[8][2];
#pragma unroll
    for (int i = 0; i < 8; i++) { U[i][0] = 0.0f; U[i][1] = 0.0f; }

#pragma unroll
    for (int r = 0; r < 8; r++) {
        const float* p = base + (size_t)r * W;
        float2 R  = __ldcs((const float2*)(p));
        float2 G  = __ldcs((const float2*)(p + CHAN));
        float2 Bv = __ldcs((const float2*)(p + 2 * CHAN));
        float g0 = 0.299f * R.x + 0.587f * G.x + 0.114f * Bv.x;
        float g1 = 0.299f * R.y + 0.587f * G.y + 0.114f * Bv.y;
#pragma unroll
        for (int i = 0; i < 8; i++) {
            const float d = sD[i * 8 + r];
            U[i][0] = fmaf(d, g0, U[i][0]);
            U[i][1] = fmaf(d, g1, U[i][1]);
        }
    }

    // Row DCT: out[i][l] = sum_k U_full[i][k] * D[l][k].
    // Each thread holds the partial over its 2 k-columns for all 8 l;
    // reduce across the 4-thread tile group, distributing l.
    const int pr   = q >> 1;    // my pair block: outputs [4*pr, 4*pr+4)
    const int half = q & 1;     // my 2 outputs within block: 2*half + {0,1}

    float* o = out + (size_t)b * CHAN
                   + (size_t)(th * 8) * W + (size_t)(tw * 8 + k0);
#pragma unroll
    for (int i = 0; i < 8; i++) {
        float p8[8];
#pragma unroll
        for (int l = 0; l < 8; l++)
            p8[l] = fmaf(U[i][0], sD[l * 8 + k0], U[i][1] * sD[l * 8 + k1]);

        // Stage A: xor 2 (across pairs) — keep my pair's 4 output columns.
        float bb[4];
#pragma unroll
        for (int c = 0; c < 4; c++) {
            float send = p8[4 * (1 - pr) + c];
            float recv = __shfl_xor_sync(0xFFFFFFFFu, send, 2);
            bb[c] = p8[4 * pr + c] + recv;
        }
        // Stage B: xor 1 (within pair) — keep my 2 output columns.
        float s0 = bb[2 * (1 - half) + 0];
        float s1 = bb[2 * (1 - half) + 1];
        float r0 = __shfl_xor_sync(0xFFFFFFFFu, s0, 1);
        float r1 = __shfl_xor_sync(0xFFFFFFFFu, s1, 1);
        float res0 = (bb[2 * half + 0] + r0) * sM[i * 8 + k0];
        float res1 = (bb[2 * half + 1] + r1) * sM[i * 8 + k1];

        __stcs((float2*)(o + (size_t)i * W), make_float2(res0, res1));
    }
}

extern "C" void kernel_launch(void* const* d_in, const int* in_sizes, int n_in,
                              void* d_out, int out_size)
{
    const float* x    = (const float*)d_in[0];
    const float* dctm = (const float*)d_in[1];
    const float* mask = (const float*)d_in[2];
    float* out = (float*)d_out;

    dct_extract_kernel<<<N_UNITS / THREADS, THREADS>>>(x, dctm, mask, out);
}

// round 4
// speedup vs baseline: 1.1033x; 1.1033x over previous
#include <cuda_runtime.h>

// DCTExtractor: gray = 0.299R + 0.587G + 0.114B over (64,3,512,512);
// per 8x8 block: D @ G @ D^T, elementwise * mask; output (64,1,512,512).
//
// Two threads per 8x8 tile (column halves) — best structure from R2.
// Column-DCT accumulated on the fly (U = D @ G over 4 cols, 32 regs);
// row-DCT partials exchanged between pair threads via shfl_xor(1)
// (compile-time register indices only — R3 showed runtime indexing
// explodes into SEL chains). launch_bounds(256,4) pins regs to 64 for
// 4 CTAs/SM; __ldcs/__stcs mark the 268MB as streaming.

#define H 512
#define W 512
#define CHAN (H * W)
#define N_TILES (64 * 64 * 64)        // 262144
#define N_UNITS (N_TILES * 2)         // 524288 half-tiles
#define THREADS 256

__global__ __launch_bounds__(THREADS, 4)
void dct_extract_kernel(const float* __restrict__ x,
                        const float* __restrict__ dctm,
                        const float* __restrict__ mask,
                        float* __restrict__ out)
{
    __shared__ float sD[64];
    __shared__ float sM[64];
    const int tid = threadIdx.x;
    if (tid < 64) {
        sD[tid] = dctm[tid];
        sM[tid] = mask[tid];
    }
    __syncthreads();

    const int gid = blockIdx.x * THREADS + tid;   // 0 .. N_UNITS-1
    const int h   = gid & 1;                      // column half
    const int id  = gid >> 1;                     // tile id
    const int tw  = id & 63;
    const int th  = (id >> 6) & 63;
    const int b   = id >> 12;
    const int hb  = h * 4;

    const float* base = x + (size_t)b * 3 * CHAN
                          + (size_t)(th * 8) * W + (size_t)(tw * 8 + hb);

    // U[i][c] = sum_r D[i][r] * gray[r][c], accumulated while streaming rows.
    float U[8][4];
#pragma unroll
    for (int i = 0; i < 8; i++)
#pragma unroll
        for (int c = 0; c < 4; c++)
            U[i][c] = 0.0f;

#pragma unroll
    for (int r = 0; r < 8; r++) {
        const float* p = base + (size_t)r * W;
        float4 R  = __ldcs((const float4*)(p));
        float4 G  = __ldcs((const float4*)(p + CHAN));
        float4 Bv = __ldcs((const float4*)(p + 2 * CHAN));
        float g0 = 0.299f * R.x + 0.587f * G.x + 0.114f * Bv.x;
        float g1 = 0.299f * R.y + 0.587f * G.y + 0.114f * Bv.y;
        float g2 = 0.299f * R.z + 0.587f * G.z + 0.114f * Bv.z;
        float g3 = 0.299f * R.w + 0.587f * G.w + 0.114f * Bv.w;
#pragma unroll
        for (int i = 0; i < 8; i++) {
            const float d = sD[i * 8 + r];
            U[i][0] = fmaf(d, g0, U[i][0]);
            U[i][1] = fmaf(d, g1, U[i][1]);
            U[i][2] = fmaf(d, g2, U[i][2]);
            U[i][3] = fmaf(d, g3, U[i][3]);
        }
    }

    // Row DCT: out[i][l] = sum_k U_full[i][k] * D[l][k], split over the pair.
    float* o = out + (size_t)b * CHAN
                   + (size_t)(th * 8) * W + (size_t)(tw * 8 + hb);
#pragma unroll
    for (int i = 0; i < 8; i++) {
        float p8[8];
#pragma unroll
        for (int l = 0; l < 8; l++) {
            float acc = 0.0f;
#pragma unroll
            for (int kc = 0; kc < 4; kc++)
                acc = fmaf(U[i][kc], sD[l * 8 + hb + kc], acc);
            p8[l] = acc;
        }
        float res[4];
#pragma unroll
        for (int j = 0; j < 4; j++) {
            // h is uniform per thread; ternary on h stays cheap (2 SEL max),
            // indices into p8 are compile-time constants.
            float send = h ? p8[j] : p8[4 + j];
            float keep = h ? p8[4 + j] : p8[j];
            float w = __shfl_xor_sync(0xFFFFFFFFu, send, 1);
            res[j] = (keep + w) * sM[i * 8 + hb + j];
        }
        __stcs((float4*)(o + (size_t)i * W),
               make_float4(res[0], res[1], res[2], res[3]));
    }
}

extern "C" void kernel_launch(void* const* d_in, const int* in_sizes, int n_in,
                              void* d_out, int out_size)
{
    const float* x    = (const float*)d_in[0];
    const float* dctm = (const float*)d_in[1];
    const float* mask = (const float*)d_in[2];
    float* out = (float*)d_out;

    dct_extract_kernel<<<N_UNITS / THREADS, THREADS>>>(x, dctm, mask, out);
}

// round 7
// speedup vs baseline: 1.2213x; 1.1069x over previous
#include <cuda_runtime.h>

// DCTExtractor: gray = 0.299R + 0.587G + 0.114B over (64,3,512,512);
// per 8x8 block: D @ G @ D^T, elementwise * mask; output (64,1,512,512).
//
// Two threads per 8x8 tile (column halves) — R2 structure (best: 45.1us).
// Changes vs R2: 128-thread CTAs (halve tail-wave quantum), __ldcs/__stcs
// streaming hints. Registers deliberately UNCONSTRAINED (R4 showed a 64-reg
// cap causes spills that cost more than the occupancy gains).

#define H 512
#define W 512
#define CHAN (H * W)
#define N_TILES (64 * 64 * 64)        // 262144
#define N_UNITS (N_TILES * 2)         // 524288 half-tiles
#define THREADS 128

__global__ __launch_bounds__(THREADS)
void dct_extract_kernel(const float* __restrict__ x,
                        const float* __restrict__ dctm,
                        const float* __restrict__ mask,
                        float* __restrict__ out)
{
    __shared__ float sD[64];
    __shared__ float sM[64];
    const int tid = threadIdx.x;
    if (tid < 64) {
        sD[tid] = dctm[tid];
        sM[tid] = mask[tid];
    }
    __syncthreads();

    const int gid = blockIdx.x * THREADS + tid;   // 0 .. N_UNITS-1
    const int h   = gid & 1;                      // column half
    const int id  = gid >> 1;                     // tile id
    const int tw  = id & 63;
    const int th  = (id >> 6) & 63;
    const int b   = id >> 12;
    const int hb  = h * 4;

    const float* base = x + (size_t)b * 3 * CHAN
                          + (size_t)(th * 8) * W + (size_t)(tw * 8 + hb);

    // U[i][c] = sum_r D[i][r] * gray[r][c], accumulated while streaming rows.
    float U[8][4];
#pragma unroll
    for (int i = 0; i < 8; i++)
#pragma unroll
        for (int c = 0; c < 4; c++)
            U[i][c] = 0.0f;

#pragma unroll
    for (int r = 0; r < 8; r++) {
        const float* p = base + (size_t)r * W;
        float4 R  = __ldcs((const float4*)(p));
        float4 G  = __ldcs((const float4*)(p + CHAN));
        float4 Bv = __ldcs((const float4*)(p + 2 * CHAN));
        float g0 = 0.299f * R.x + 0.587f * G.x + 0.114f * Bv.x;
        float g1 = 0.299f * R.y + 0.587f * G.y + 0.114f * Bv.y;
        float g2 = 0.299f * R.z + 0.587f * G.z + 0.114f * Bv.z;
        float g3 = 0.299f * R.w + 0.587f * G.w + 0.114f * Bv.w;
#pragma unroll
        for (int i = 0; i < 8; i++) {
            const float d = sD[i * 8 + r];
            U[i][0] = fmaf(d, g0, U[i][0]);
            U[i][1] = fmaf(d, g1, U[i][1]);
            U[i][2] = fmaf(d, g2, U[i][2]);
            U[i][3] = fmaf(d, g3, U[i][3]);
        }
    }

    // Row DCT: out[i][l] = sum_k U_full[i][k] * D[l][k], split over the pair.
    float* o = out + (size_t)b * CHAN
                   + (size_t)(th * 8) * W + (size_t)(tw * 8 + hb);
#pragma unroll
    for (int i = 0; i < 8; i++) {
        float p8[8];
#pragma unroll
        for (int l = 0; l < 8; l++) {
            float acc = 0.0f;
#pragma unroll
            for (int kc = 0; kc < 4; kc++)
                acc = fmaf(U[i][kc], sD[l * 8 + hb + kc], acc);
            p8[l] = acc;
        }
        float res[4];
#pragma unroll
        for (int j = 0; j < 4; j++) {
            // h is uniform per thread; indices into p8 are compile-time.
            float send = h ? p8[j] : p8[4 + j];
            float keep = h ? p8[4 + j] : p8[j];
            float w = __shfl_xor_sync(0xFFFFFFFFu, send, 1);
            res[j] = (keep + w) * sM[i * 8 + hb + j];
        }
        __stcs((float4*)(o + (size_t)i * W),
               make_float4(res[0], res[1], res[2], res[3]));
    }
}

extern "C" void kernel_launch(void* const* d_in, const int* in_sizes, int n_in,
                              void* d_out, int out_size)
{
    const float* x    = (const float*)d_in[0];
    const float* dctm = (const float*)d_in[1];
    const float* mask = (const float*)d_in[2];
    float* out = (float*)d_out;

    dct_extract_kernel<<<N_UNITS / THREADS, THREADS>>>(x, dctm, mask, out);
}

// round 8
// speedup vs baseline: 1.2690x; 1.0391x over previous
#include <cuda_runtime.h>

// DCTExtractor: gray = 0.299R + 0.587G + 0.114B over (64,3,512,512);
// per 8x8 block: D @ G @ D^T, elementwise * mask; output (64,1,512,512).
//
// Two threads per 8x8 tile (column halves) — R2/R7 structure.
// R8 change: 64-thread CTAs (grid 8192). Per-CTA DRAM work halves to 32KB,
// halving T_CTA (~8us -> ~4us) and thus the dynamic-scheduling straggler
// tail, which is the only remaining recoverable time (DRAM% pinned at 68.4
// across occ 22-45% in R1-R7). Registers unconstrained; __ldcs/__stcs
// streaming hints retained.

#define H 512
#define W 512
#define CHAN (H * W)
#define N_TILES (64 * 64 * 64)        // 262144
#define N_UNITS (N_TILES * 2)         // 524288 half-tiles
#define THREADS 64

__global__ __launch_bounds__(THREADS)
void dct_extract_kernel(const float* __restrict__ x,
                        const float* __restrict__ dctm,
                        const float* __restrict__ mask,
                        float* __restrict__ out)
{
    __shared__ float sD[64];
    __shared__ float sM[64];
    const int tid = threadIdx.x;
    // 64 threads: each loads one element of each table.
    sD[tid] = dctm[tid];
    sM[tid] = mask[tid];
    __syncthreads();

    const int gid = blockIdx.x * THREADS + tid;   // 0 .. N_UNITS-1
    const int h   = gid & 1;                      // column half
    const int id  = gid >> 1;                     // tile id
    const int tw  = id & 63;
    const int th  = (id >> 6) & 63;
    const int b   = id >> 12;
    const int hb  = h * 4;

    const float* base = x + (size_t)b * 3 * CHAN
                          + (size_t)(th * 8) * W + (size_t)(tw * 8 + hb);

    // U[i][c] = sum_r D[i][r] * gray[r][c], accumulated while streaming rows.
    float U[8][4];
#pragma unroll
    for (int i = 0; i < 8; i++)
#pragma unroll
        for (int c = 0; c < 4; c++)
            U[i][c] = 0.0f;

#pragma unroll
    for (int r = 0; r < 8; r++) {
        const float* p = base + (size_t)r * W;
        float4 R  = __ldcs((const float4*)(p));
        float4 G  = __ldcs((const float4*)(p + CHAN));
        float4 Bv = __ldcs((const float4*)(p + 2 * CHAN));
        float g0 = 0.299f * R.x + 0.587f * G.x + 0.114f * Bv.x;
        float g1 = 0.299f * R.y + 0.587f * G.y + 0.114f * Bv.y;
        float g2 = 0.299f * R.z + 0.587f * G.z + 0.114f * Bv.z;
        float g3 = 0.299f * R.w + 0.587f * G.w + 0.114f * Bv.w;
#pragma unroll
        for (int i = 0; i < 8; i++) {
            const float d = sD[i * 8 + r];
            U[i][0] = fmaf(d, g0, U[i][0]);
            U[i][1] = fmaf(d, g1, U[i][1]);
            U[i][2] = fmaf(d, g2, U[i][2]);
            U[i][3] = fmaf(d, g3, U[i][3]);
        }
    }

    // Row DCT: out[i][l] = sum_k U_full[i][k] * D[l][k], split over the pair.
    float* o = out + (size_t)b * CHAN
                   + (size_t)(th * 8) * W + (size_t)(tw * 8 + hb);
#pragma unroll
    for (int i = 0; i < 8; i++) {
        float p8[8];
#pragma unroll
        for (int l = 0; l < 8; l++) {
            float acc = 0.0f;
#pragma unroll
            for (int kc = 0; kc < 4; kc++)
                acc = fmaf(U[i][kc], sD[l * 8 + hb + kc], acc);
            p8[l] = acc;
        }
        float res[4];
#pragma unroll
        for (int j = 0; j < 4; j++) {
            // h is uniform per thread; indices into p8 are compile-time.
            float send = h ? p8[j] : p8[4 + j];
            float keep = h ? p8[4 + j] : p8[j];
            float w = __shfl_xor_sync(0xFFFFFFFFu, send, 1);
            res[j] = (keep + w) * sM[i * 8 + hb + j];
        }
        __stcs((float4*)(o + (size_t)i * W),
               make_float4(res[0], res[1], res[2], res[3]));
    }
}

extern "C" void kernel_launch(void* const* d_in, const int* in_sizes, int n_in,
                              void* d_out, int out_size)
{
    const float* x    = (const float*)d_in[0];
    const float* dctm = (const float*)d_in[1];
    const float* mask = (const float*)d_in[2];
    float* out = (float*)d_out;

    dct_extract_kernel<<<N_UNITS / THREADS, THREADS>>>(x, dctm, mask, out);
}